// round 14
// baseline (speedup 1.0000x reference)
#include <cuda_runtime.h>
#include <cuda_bf16.h>
#include <math_constants.h>

#define NB 4
#define CC 16
#define HW 4096
#define IMG_ELEMS 262144
#define IMG_BYTES 1048576
#define OUT_ELEMS_EXPECTED 49152

// Fully fused PatchMatch NN kernel. NO device-global scratch (suspected cause
// of 13 rounds of silent failure: lazy module-load allocation of 19MB of
// __device__ arrays tripping the harness allocation guard).
//
// Block = (b, yq, half): 32 queries (one half image row) x all 4096 targets.
// 128 threads: tx = tid&15 (4 targets each), ty = tid>>4 (4 queries each).
__global__ __launch_bounds__(128) void nn_fused(const float* __restrict__ S,
                                                const float* __restrict__ T,
                                                float* __restrict__ out,
                                                int out_elems) {
    int blk  = blockIdx.x;          // ((b*64 + yq)*2 + half)
    int half = blk & 1;
    int yq   = (blk >> 1) & 63;
    int b    = blk >> 7;
    int qx0  = half * 32;

    int tid = threadIdx.x;
    int tx  = tid & 15;
    int ty  = tid >> 4;

    __shared__ float srow[CC][3][64];               // s rows yq-1..yq+1 (clamped)
    __shared__ float trow[CC][3][64];               // t rows yt-1..yt+1 (clamped)
    __shared__ __align__(16) float Qs[16][32];      // query descriptor k-tile
    __shared__ __align__(16) float Ps[16][64];      // target descriptor k-tile
    __shared__ float qpart[4][32];
    __shared__ float qn32[32];
    __shared__ float pnpart[2][64];
    __shared__ float pn64[64];
    __shared__ float redv[32][17];
    __shared__ int   redi[32][17];

    const float* Sb = S + (size_t)b * CC * HW;
    const float* Tb = T + (size_t)b * CC * HW;

    // Cache the 3 source rows (replicate-clamped), full 64-wide.
#pragma unroll
    for (int u = 0; u < 24; u++) {
        int e = tid + u * 128;       // 0..3071
        int x = e & 63;
        int r = (e >> 6) % 3;
        int c = e / 192;
        int yy = min(max(yq - 1 + r, 0), 63);
        srow[c][r][x] = Sb[(c * 64 + yy) * 64 + x];
    }
    __syncthreads();

    // Query norms for this block's 32 queries (4-way k-split).
    {
        int xq = tid & 31, g = tid >> 5;
        int xabs = qx0 + xq;
        float sum = 0.f;
        for (int k = g * 36; k < g * 36 + 36; k++) {
            int c = k / 9, p = k % 9;
            int dy = p / 3 - 1, dx = p % 3 - 1;
            int xx = min(max(xabs + dx, 0), 63);
            float v = srow[c][1 + dy][xx];
            sum += v * v;
        }
        qpart[g][xq] = sum;
    }
    __syncthreads();
    if (tid < 32)
        qn32[tid] = ((qpart[0][tid] + qpart[1][tid]) + qpart[2][tid]) + qpart[3][tid];
    __syncthreads();

    float myqn[4];
#pragma unroll
    for (int r = 0; r < 4; r++) myqn[r] = qn32[ty * 4 + r];

    float bestv[4];
    int   besti[4];
#pragma unroll
    for (int r = 0; r < 4; r++) { bestv[r] = CUDART_INF_F; besti[r] = 0; }

    for (int yt = 0; yt < 64; yt++) {
        __syncthreads();   // all readers of trow/pn64 from prev iter done
        // Cache the 3 target rows (replicate-clamped).
#pragma unroll
        for (int u = 0; u < 24; u++) {
            int e = tid + u * 128;
            int x = e & 63;
            int r = (e >> 6) % 3;
            int c = e / 192;
            int yy = min(max(yt - 1 + r, 0), 63);
            trow[c][r][x] = Tb[(c * 64 + yy) * 64 + x];
        }
        __syncthreads();

        // Target norms for this row (2-way k-split over 128 threads).
        {
            int g = tid >> 6, x = tid & 63;
            float sum = 0.f;
            for (int k = g * 72; k < g * 72 + 72; k++) {
                int c = k / 9, p = k % 9;
                int dy = p / 3 - 1, dx = p % 3 - 1;
                int xx = min(max(x + dx, 0), 63);
                float v = trow[c][1 + dy][xx];
                sum += v * v;
            }
            pnpart[g][x] = sum;
        }
        __syncthreads();
        if (tid < 64) pn64[tid] = pnpart[0][tid] + pnpart[1][tid];

        float acc[4][4];
#pragma unroll
        for (int r = 0; r < 4; r++)
#pragma unroll
            for (int j = 0; j < 4; j++) acc[r][j] = 0.f;

        for (int k0 = 0; k0 < 144; k0 += 16) {
            __syncthreads();
            // Materialize Qs (512 elems) and Ps (1024 elems) from row caches.
#pragma unroll
            for (int u = 0; u < 4; u++) {
                int e  = tid + u * 128;        // 0..511
                int kk = e >> 5, xq = e & 31;
                int k  = k0 + kk;
                int c = k / 9, p = k % 9;
                int dyy = p / 3 - 1, dxx = p % 3 - 1;
                int xx = min(max(qx0 + xq + dxx, 0), 63);
                Qs[kk][xq] = srow[c][1 + dyy][xx];
            }
#pragma unroll
            for (int u = 0; u < 8; u++) {
                int e  = tid + u * 128;        // 0..1023
                int kk = e >> 6, x = e & 63;
                int k  = k0 + kk;
                int c = k / 9, p = k % 9;
                int dyy = p / 3 - 1, dxx = p % 3 - 1;
                int xx = min(max(x + dxx, 0), 63);
                Ps[kk][x] = trow[c][1 + dyy][xx];
            }
            __syncthreads();
#pragma unroll
            for (int kk = 0; kk < 16; kk++) {
                float4 q4 = *(const float4*)&Qs[kk][ty * 4];
                float4 p4 = *(const float4*)&Ps[kk][tx * 4];
                float qv[4] = {q4.x, q4.y, q4.z, q4.w};
                float pv[4] = {p4.x, p4.y, p4.z, p4.w};
#pragma unroll
                for (int r = 0; r < 4; r++)
#pragma unroll
                    for (int j = 0; j < 4; j++)
                        acc[r][j] = fmaf(qv[r], pv[j], acc[r][j]);
            }
        }

        // d2 = (qn - 2*cross) + pn; NaN-robust update, ascending jg per thread.
#pragma unroll
        for (int j = 0; j < 4; j++) {
            int jg = yt * 64 + tx * 4 + j;
            float pnj = pn64[tx * 4 + j];
#pragma unroll
            for (int r = 0; r < 4; r++) {
                float d2 = (myqn[r] - 2.0f * acc[r][j]) + pnj;
                if (!(d2 >= bestv[r])) { bestv[r] = d2; besti[r] = jg; }
            }
        }
    }

    // Cross-thread reduction over the 16 tx lanes per query.
    __syncthreads();
#pragma unroll
    for (int r = 0; r < 4; r++) {
        redv[ty * 4 + r][tx] = bestv[r];
        redi[ty * 4 + r][tx] = besti[r];
    }
    __syncthreads();

    if (tid < 32) {
        float bv = redv[tid][0];
        int   bi = redi[tid][0];
#pragma unroll
        for (int u = 1; u < 16; u++) {
            float v  = redv[tid][u];
            int   id = redi[tid][u];
            if (v < bv || (v == bv && id < bi)) { bv = v; bi = id; }
        }
        int gi = yq * 64 + qx0 + tid;
        int yb = bi >> 6;
        int xb = bi & 63;
        // float32 combined layout: [nnf (n,2,h,w)] then [nnd (n,1,h,w)].
        int o0 = (b * 2 + 0) * HW + gi;
        int o1 = (b * 2 + 1) * HW + gi;
        int o2 = NB * 2 * HW + b * HW + gi;
        if (o0 < out_elems) out[o0] = (float)yb;
        if (o1 < out_elems) out[o1] = (float)xb;
        if (o2 < out_elems) out[o2] = bv;
    }
}

extern "C" void kernel_launch(void* const* d_in, const int* in_sizes, int n_in,
                              void* d_out, int out_size) {
    // Robust input selection (element or byte conventions, fallback = two
    // largest buffers in order of appearance).
    int ia = -1, ib = -1;
    for (int i = 0; i < n_in; i++) {
        if (in_sizes[i] == IMG_ELEMS || in_sizes[i] == IMG_BYTES) {
            if (ia < 0) ia = i;
            else if (ib < 0) ib = i;
        }
    }
    if (ib < 0) {
        ia = -1; ib = -1;
        for (int i = 0; i < n_in; i++) {
            if (ia < 0 || in_sizes[i] > in_sizes[ia]) { ib = ia; ia = i; }
            else if (ib < 0 || in_sizes[i] > in_sizes[ib]) { ib = i; }
        }
        if (ia > ib) { int tmp = ia; ia = ib; ib = tmp; }
    }
    const float* s = (const float*)d_in[ia];
    const float* t = (const float*)d_in[ib];

    float* out = (float*)d_out;
    int out_elems = out_size < OUT_ELEMS_EXPECTED ? out_size : OUT_ELEMS_EXPECTED;

    nn_fused<<<NB * 64 * 2, 128>>>(s, t, out, out_elems);
}

// round 15
// speedup vs baseline: 1.4860x; 1.4860x over previous
#include <cuda_runtime.h>
#include <math_constants.h>

#define NB 4
#define CC 16
#define HW 4096
#define IMG_ELEMS 262144
#define IMG_BYTES 1048576
#define OUT_ELEMS_EXPECTED 49152
#define PW 72   // padded row width: x index xi = 4 + x, valid xi 3..68 used

typedef unsigned long long ull;

__device__ __forceinline__ ull pack2(float lo, float hi) {
    ull r;
    asm("mov.b64 %0, {%1, %2};" : "=l"(r) : "f"(lo), "f"(hi));
    return r;
}
__device__ __forceinline__ void unpack2(ull v, float& lo, float& hi) {
    asm("mov.b64 {%0, %1}, %2;" : "=f"(lo), "=f"(hi) : "l"(v));
}
__device__ __forceinline__ ull ffma2(ull a, ull b, ull c) {
    ull d;
    asm("fma.rn.f32x2 %0, %1, %2, %3;" : "=l"(d) : "l"(a), "l"(b), "l"(c));
    return d;
}

// Block = (b, yq, half): 32 queries (half of image row yq) x all 4096 targets.
// 128 threads: tx = tid&15 -> targets {tx, tx+16, tx+32, tx+48} per row;
//              ty = tid>>4 (0..7) -> queries qx0 + ty*4 .. +3 (as 2 f32x2 pairs).
__global__ __launch_bounds__(128, 4) void nn_fused(const float* __restrict__ S,
                                                   const float* __restrict__ T,
                                                   float* __restrict__ out,
                                                   int out_elems) {
    int blk  = blockIdx.x;          // ((b*64 + yq)*2 + half)
    int half = blk & 1;
    int yq   = (blk >> 1) & 63;
    int b    = blk >> 7;
    int qx0  = half * 32;

    int tid = threadIdx.x;
    int tx  = tid & 15;
    int ty  = tid >> 4;

    // Padded caches: clamp is baked in at fill time -> zero ALU in hot loop.
    __shared__ float  srow[CC * 3 * PW];          // source rows yq-1..yq+1
    __shared__ float2 trow2[CC * 3 * PW];         // target rows (ring by r%3), (v,v) pairs
    __shared__ float  qpart[4][32];
    __shared__ float  qn32[32];
    __shared__ float  pnpart[2][64];
    __shared__ float  redv[32][17];
    __shared__ int    redi[32][17];

    const float* Sb = S + (size_t)b * CC * HW;
    const float* Tb = T + (size_t)b * CC * HW;

    // ---- fill srow (once): 16c x 3 rows x 72 padded cols = 3456 floats ----
#pragma unroll
    for (int u = 0; u < 27; u++) {
        int e = tid + u * 128;                     // 0..3455
        int c   = e / (3 * PW);
        int rem = e - c * (3 * PW);
        int r   = rem / PW;
        int xi  = rem - r * PW;
        int ry  = min(max(yq + r - 1, 0), 63);
        int xx  = min(max(xi - 4, 0), 63);
        srow[e] = Sb[(c * 64 + ry) * 64 + xx];
    }

    // ---- ring pre-fill trow rows r=-1 (slot 2) and r=0 (slot 0) ----
#pragma unroll
    for (int pre = 0; pre < 2; pre++) {
        int r_un = pre - 1;                        // -1, 0
        int slot = ((r_un % 3) + 3) % 3;
        int ry   = max(r_un, 0);
#pragma unroll
        for (int u = 0; u < 9; u++) {
            int e = tid + u * 128;                 // 0..1151
            int c  = e / PW;
            int xi = e - c * PW;
            int xx = min(max(xi - 4, 0), 63);
            float v = Tb[(c * 64 + ry) * 64 + xx];
            trow2[(c * 3 + slot) * PW + xi] = make_float2(v, v);
        }
    }
    __syncthreads();

    // ---- query norms (4-way k-split, same split/order as passing R14) ----
    {
        int xq = tid & 31, g = tid >> 5;
        int xabs = qx0 + xq;
        float sum = 0.f;
        for (int c = g * 4; c < g * 4 + 4; c++)
#pragma unroll
            for (int dy = 0; dy < 3; dy++)
#pragma unroll
                for (int dx = 0; dx < 3; dx++) {
                    float v = srow[(c * 3 + dy) * PW + 3 + xabs + dx];
                    sum += v * v;
                }
        qpart[g][xq] = sum;
    }
    __syncthreads();
    if (tid < 32)
        qn32[tid] = ((qpart[0][tid] + qpart[1][tid]) + qpart[2][tid]) + qpart[3][tid];
    __syncthreads();

    float myqn[4];
#pragma unroll
    for (int r = 0; r < 4; r++) myqn[r] = qn32[ty * 4 + r];

    float bestv[4];
    int   besti[4];
#pragma unroll
    for (int r = 0; r < 4; r++) { bestv[r] = CUDART_INF_F; besti[r] = 0; }

    const int ql = qx0 + ty * 4;                   // this thread's first query x

    for (int yt = 0; yt < 64; yt++) {
        __syncthreads();                           // prev readers of recycled slot done
        // fill ring slot for unclamped row yt+1
        {
            int r_un = yt + 1;
            int slot = r_un % 3;
            int ry   = min(r_un, 63);
#pragma unroll
            for (int u = 0; u < 9; u++) {
                int e = tid + u * 128;
                int c  = e / PW;
                int xi = e - c * PW;
                int xx = min(max(xi - 4, 0), 63);
                float v = Tb[(c * 64 + ry) * 64 + xx];
                trow2[(c * 3 + slot) * PW + xi] = make_float2(v, v);
            }
        }
        __syncthreads();

        int s0 = (yt + 2) % 3;                     // row yt-1
        int s1 = yt % 3;                           // row yt
        int s2 = (yt + 1) % 3;                     // row yt+1

        // ---- target norms: 2-way k-split (c 0..7 | 8..15), R14 order ----
        {
            int g = tid >> 6, x = tid & 63;
            float sum = 0.f;
            for (int c = g * 8; c < g * 8 + 8; c++) {
#pragma unroll
                for (int dy = 0; dy < 3; dy++) {
                    int sl = (dy == 0) ? s0 : (dy == 1) ? s1 : s2;
                    const float2* rp = trow2 + (c * 3 + sl) * PW + 3 + x;
#pragma unroll
                    for (int dx = 0; dx < 3; dx++) {
                        float v = rp[dx].x;
                        sum += v * v;
                    }
                }
            }
            pnpart[g][x] = sum;
        }

        // ---- cross inner product: FFMA2, (c,dy,dx) ascending == k ascending ----
        ull acc2[2][4];
#pragma unroll
        for (int p = 0; p < 2; p++)
#pragma unroll
            for (int j = 0; j < 4; j++) acc2[p][j] = 0ull;

#pragma unroll 1
        for (int c = 0; c < CC; c++) {
            const float* qb = srow + (c * 3) * PW + 3 + ql;
            const ull* tb0 = (const ull*)(trow2 + (c * 3 + s0) * PW + 3 + tx);
            const ull* tb1 = (const ull*)(trow2 + (c * 3 + s1) * PW + 3 + tx);
            const ull* tb2 = (const ull*)(trow2 + (c * 3 + s2) * PW + 3 + tx);
#pragma unroll
            for (int dy = 0; dy < 3; dy++) {
                const float* qrow = qb + dy * PW;
                const ull* trp = (dy == 0) ? tb0 : (dy == 1) ? tb1 : tb2;
                float q0 = qrow[0], q1 = qrow[1], q2 = qrow[2],
                      q3 = qrow[3], q4 = qrow[4], q5 = qrow[5];
                ull P01 = pack2(q0, q1), P12 = pack2(q1, q2), P23 = pack2(q2, q3),
                    P34 = pack2(q3, q4), P45 = pack2(q4, q5);
#pragma unroll
                for (int dx = 0; dx < 3; dx++) {
                    ull qa = (dx == 0) ? P01 : (dx == 1) ? P12 : P23;
                    ull qb2 = (dx == 0) ? P23 : (dx == 1) ? P34 : P45;
                    ull t0 = trp[dx + 0];
                    ull t1 = trp[dx + 16];
                    ull t2 = trp[dx + 32];
                    ull t3 = trp[dx + 48];
                    acc2[0][0] = ffma2(qa,  t0, acc2[0][0]);
                    acc2[1][0] = ffma2(qb2, t0, acc2[1][0]);
                    acc2[0][1] = ffma2(qa,  t1, acc2[0][1]);
                    acc2[1][1] = ffma2(qb2, t1, acc2[1][1]);
                    acc2[0][2] = ffma2(qa,  t2, acc2[0][2]);
                    acc2[1][2] = ffma2(qb2, t2, acc2[1][2]);
                    acc2[0][3] = ffma2(qa,  t3, acc2[0][3]);
                    acc2[1][3] = ffma2(qb2, t3, acc2[1][3]);
                }
            }
        }
        __syncthreads();                           // pnpart ready for all readers

        // ---- d2 + NaN-robust argmin (ascending index within thread) ----
#pragma unroll
        for (int j = 0; j < 4; j++) {
            int xt = tx + 16 * j;
            float pnj = pnpart[0][xt] + pnpart[1][xt];
            int jg = yt * 64 + xt;
            float c0, c1, c2, c3;
            unpack2(acc2[0][j], c0, c1);
            unpack2(acc2[1][j], c2, c3);
            float cr[4] = {c0, c1, c2, c3};
#pragma unroll
            for (int r = 0; r < 4; r++) {
                float d2 = (myqn[r] - 2.0f * cr[r]) + pnj;
                if (!(d2 >= bestv[r])) { bestv[r] = d2; besti[r] = jg; }
            }
        }
    }

    // ---- cross-thread reduction over 16 tx lanes per query ----
    __syncthreads();
#pragma unroll
    for (int r = 0; r < 4; r++) {
        redv[ty * 4 + r][tx] = bestv[r];
        redi[ty * 4 + r][tx] = besti[r];
    }
    __syncthreads();

    if (tid < 32) {
        float bv = redv[tid][0];
        int   bi = redi[tid][0];
#pragma unroll
        for (int u = 1; u < 16; u++) {
            float v  = redv[tid][u];
            int   id = redi[tid][u];
            if (v < bv || (v == bv && id < bi)) { bv = v; bi = id; }
        }
        int gi = yq * 64 + qx0 + tid;
        int yb = bi >> 6;
        int xb = bi & 63;
        int o0 = (b * 2 + 0) * HW + gi;
        int o1 = (b * 2 + 1) * HW + gi;
        int o2 = NB * 2 * HW + b * HW + gi;
        if (o0 < out_elems) out[o0] = (float)yb;
        if (o1 < out_elems) out[o1] = (float)xb;
        if (o2 < out_elems) out[o2] = bv;
    }
}

extern "C" void kernel_launch(void* const* d_in, const int* in_sizes, int n_in,
                              void* d_out, int out_size) {
    int ia = -1, ib = -1;
    for (int i = 0; i < n_in; i++) {
        if (in_sizes[i] == IMG_ELEMS || in_sizes[i] == IMG_BYTES) {
            if (ia < 0) ia = i;
            else if (ib < 0) ib = i;
        }
    }
    if (ib < 0) {
        ia = -1; ib = -1;
        for (int i = 0; i < n_in; i++) {
            if (ia < 0 || in_sizes[i] > in_sizes[ia]) { ib = ia; ia = i; }
            else if (ib < 0 || in_sizes[i] > in_sizes[ib]) { ib = i; }
        }
        if (ia > ib) { int tmp = ia; ia = ib; ib = tmp; }
    }
    const float* s = (const float*)d_in[ia];
    const float* t = (const float*)d_in[ib];

    float* out = (float*)d_out;
    int out_elems = out_size < OUT_ELEMS_EXPECTED ? out_size : OUT_ELEMS_EXPECTED;

    nn_fused<<<NB * 64 * 2, 128>>>(s, t, out, out_elems);
}

// round 16
// speedup vs baseline: 1.8156x; 1.2218x over previous
#include <cuda_runtime.h>
#include <math_constants.h>

#define NB 4
#define CC 16
#define HW 4096
#define IMG_ELEMS 262144
#define IMG_BYTES 1048576
#define OUT_ELEMS_EXPECTED 49152
#define PW 72   // padded row width: xi = x + 4, valid xi 3..68 used

typedef unsigned long long ull;

__device__ __forceinline__ ull pack2(float lo, float hi) {
    ull r;
    asm("mov.b64 %0, {%1, %2};" : "=l"(r) : "f"(lo), "f"(hi));
    return r;
}
__device__ __forceinline__ void unpack2(ull v, float& lo, float& hi) {
    asm("mov.b64 {%0, %1}, %2;" : "=f"(lo), "=f"(hi) : "l"(v));
}
__device__ __forceinline__ ull ffma2(ull a, ull b, ull c) {
    ull d;
    asm("fma.rn.f32x2 %0, %1, %2, %3;" : "=l"(d) : "l"(a), "l"(b), "l"(c));
    return d;
}

// Block = (b, yq): full query row (64 q) x all 4096 targets. Grid = 256.
// 128 threads: tx = tid&15 -> targets {tx, tx+16, tx+32, tx+48} per row;
//              ty = tid>>4 (0..7) -> 8 queries ty*8..ty*8+7 as 4 f32x2 pairs.
__global__ __launch_bounds__(128, 2) void nn_fused(const float* __restrict__ S,
                                                   const float* __restrict__ T,
                                                   float* __restrict__ out,
                                                   int out_elems) {
    int yq = blockIdx.x & 63;
    int b  = blockIdx.x >> 6;

    int tid = threadIdx.x;
    int tx  = tid & 15;
    int ty  = tid >> 4;

    __shared__ float  srow[CC * 3 * PW];        // source rows yq-1..yq+1 (padded/clamped)
    __shared__ float2 trow2[CC * 3 * PW];       // target rows, ring by r%3, (v,v) pairs
    __shared__ float  qnpart[2][64];
    __shared__ float  qn64[64];
    __shared__ float  pnpart[2][64];

    const float* Sb = S + (size_t)b * CC * HW;
    const float* Tb = T + (size_t)b * CC * HW;

    // ---- fill srow: 16c x 3 rows x 72 cols = 3456 floats ----
#pragma unroll
    for (int u = 0; u < 27; u++) {
        int e = tid + u * 128;
        int c   = e / (3 * PW);
        int rem = e - c * (3 * PW);
        int r   = rem / PW;
        int xi  = rem - r * PW;
        int ry  = min(max(yq + r - 1, 0), 63);
        int xx  = min(max(xi - 4, 0), 63);
        srow[e] = Sb[(c * 64 + ry) * 64 + xx];
    }

    // ---- ring pre-fill trow rows -1 (slot 2) and 0 (slot 0) ----
#pragma unroll
    for (int pre = 0; pre < 2; pre++) {
        int r_un = pre - 1;
        int slot = ((r_un % 3) + 3) % 3;
        int ry   = max(r_un, 0);
#pragma unroll
        for (int u = 0; u < 9; u++) {
            int e = tid + u * 128;
            int c  = e / PW;
            int xi = e - c * PW;
            int xx = min(max(xi - 4, 0), 63);
            float v = Tb[(c * 64 + ry) * 64 + xx];
            trow2[(c * 3 + slot) * PW + xi] = make_float2(v, v);
        }
    }
    __syncthreads();

    // ---- query norms for 64 queries (2-way c-split) ----
    {
        int g = tid >> 6, x = tid & 63;
        float sum = 0.f;
        for (int c = g * 8; c < g * 8 + 8; c++)
#pragma unroll
            for (int dy = 0; dy < 3; dy++)
#pragma unroll
                for (int dx = 0; dx < 3; dx++) {
                    float v = srow[(c * 3 + dy) * PW + 3 + x + dx];
                    sum += v * v;
                }
        qnpart[g][x] = sum;
    }
    __syncthreads();
    if (tid < 64) qn64[tid] = qnpart[0][tid] + qnpart[1][tid];
    __syncthreads();

    const int ql = ty * 8;
    float myqn[8];
#pragma unroll
    for (int r = 0; r < 8; r++) myqn[r] = qn64[ql + r];

    float bestv[8];
    int   besti[8];
#pragma unroll
    for (int r = 0; r < 8; r++) { bestv[r] = CUDART_INF_F; besti[r] = 0; }

    for (int yt = 0; yt < 64; yt++) {
        __syncthreads();                        // recycled-slot readers done
        {
            int r_un = yt + 1;
            int slot = r_un % 3;
            int ry   = min(r_un, 63);
#pragma unroll
            for (int u = 0; u < 9; u++) {
                int e = tid + u * 128;
                int c  = e / PW;
                int xi = e - c * PW;
                int xx = min(max(xi - 4, 0), 63);
                float v = Tb[(c * 64 + ry) * 64 + xx];
                trow2[(c * 3 + slot) * PW + xi] = make_float2(v, v);
            }
        }
        __syncthreads();

        int s0 = (yt + 2) % 3;                  // row yt-1
        int s1 = yt % 3;                        // row yt
        int s2 = (yt + 1) % 3;                  // row yt+1

        // ---- target norms (2-way c-split) ----
        {
            int g = tid >> 6, x = tid & 63;
            float sum = 0.f;
            for (int c = g * 8; c < g * 8 + 8; c++) {
#pragma unroll
                for (int dy = 0; dy < 3; dy++) {
                    int sl = (dy == 0) ? s0 : (dy == 1) ? s1 : s2;
                    const float2* rp = trow2 + (c * 3 + sl) * PW + 3 + x;
#pragma unroll
                    for (int dx = 0; dx < 3; dx++) {
                        float v = rp[dx].x;
                        sum += v * v;
                    }
                }
            }
            pnpart[g][x] = sum;
        }

        // ---- cross: 8q x 4t per thread, FFMA2, (c,dy,dx) ascending ----
        ull acc2[4][4];
#pragma unroll
        for (int p = 0; p < 4; p++)
#pragma unroll
            for (int j = 0; j < 4; j++) acc2[p][j] = 0ull;

#pragma unroll 1
        for (int c = 0; c < CC; c++) {
            const float* qb = srow + (c * 3) * PW + 3 + ql;
            const ull* tb0 = (const ull*)(trow2 + (c * 3 + s0) * PW + 3 + tx);
            const ull* tb1 = (const ull*)(trow2 + (c * 3 + s1) * PW + 3 + tx);
            const ull* tb2 = (const ull*)(trow2 + (c * 3 + s2) * PW + 3 + tx);
#pragma unroll
            for (int dy = 0; dy < 3; dy++) {
                const float* qrow = qb + dy * PW;
                const ull* trp = (dy == 0) ? tb0 : (dy == 1) ? tb1 : tb2;
                float q0 = qrow[0], q1 = qrow[1], q2 = qrow[2], q3 = qrow[3], q4 = qrow[4];
                float q5 = qrow[5], q6 = qrow[6], q7 = qrow[7], q8 = qrow[8], q9 = qrow[9];
                // P[p] = queries (2p-1, 2p) rel. ql ; Q[p] = (2p, 2p+1)
                ull P0 = pack2(q0, q1), P1 = pack2(q2, q3), P2 = pack2(q4, q5),
                    P3 = pack2(q6, q7), P4 = pack2(q8, q9);
                ull Q0 = pack2(q1, q2), Q1 = pack2(q3, q4), Q2 = pack2(q5, q6),
                    Q3 = pack2(q7, q8);
#pragma unroll
                for (int dx = 0; dx < 3; dx++) {
                    ull qp0 = (dx == 0) ? P0 : (dx == 1) ? Q0 : P1;
                    ull qp1 = (dx == 0) ? P1 : (dx == 1) ? Q1 : P2;
                    ull qp2 = (dx == 0) ? P2 : (dx == 1) ? Q2 : P3;
                    ull qp3 = (dx == 0) ? P3 : (dx == 1) ? Q3 : P4;
                    ull t0 = trp[dx + 0];
                    ull t1 = trp[dx + 16];
                    ull t2 = trp[dx + 32];
                    ull t3 = trp[dx + 48];
                    acc2[0][0] = ffma2(qp0, t0, acc2[0][0]);
                    acc2[1][0] = ffma2(qp1, t0, acc2[1][0]);
                    acc2[2][0] = ffma2(qp2, t0, acc2[2][0]);
                    acc2[3][0] = ffma2(qp3, t0, acc2[3][0]);
                    acc2[0][1] = ffma2(qp0, t1, acc2[0][1]);
                    acc2[1][1] = ffma2(qp1, t1, acc2[1][1]);
                    acc2[2][1] = ffma2(qp2, t1, acc2[2][1]);
                    acc2[3][1] = ffma2(qp3, t1, acc2[3][1]);
                    acc2[0][2] = ffma2(qp0, t2, acc2[0][2]);
                    acc2[1][2] = ffma2(qp1, t2, acc2[1][2]);
                    acc2[2][2] = ffma2(qp2, t2, acc2[2][2]);
                    acc2[3][2] = ffma2(qp3, t2, acc2[3][2]);
                    acc2[0][3] = ffma2(qp0, t3, acc2[0][3]);
                    acc2[1][3] = ffma2(qp1, t3, acc2[1][3]);
                    acc2[2][3] = ffma2(qp2, t3, acc2[2][3]);
                    acc2[3][3] = ffma2(qp3, t3, acc2[3][3]);
                }
            }
        }
        __syncthreads();                        // pnpart ready

        // ---- d2 + NaN-robust argmin (ascending index per thread) ----
#pragma unroll
        for (int j = 0; j < 4; j++) {
            int xt = tx + 16 * j;
            float pnj = pnpart[0][xt] + pnpart[1][xt];
            int jg = yt * 64 + xt;
#pragma unroll
            for (int p = 0; p < 4; p++) {
                float clo, chi;
                unpack2(acc2[p][j], clo, chi);
                float d2a = (myqn[2 * p] - 2.0f * clo) + pnj;
                float d2b = (myqn[2 * p + 1] - 2.0f * chi) + pnj;
                if (!(d2a >= bestv[2 * p]))     { bestv[2 * p] = d2a;     besti[2 * p] = jg; }
                if (!(d2b >= bestv[2 * p + 1])) { bestv[2 * p + 1] = d2b; besti[2 * p + 1] = jg; }
            }
        }
    }

    // ---- shuffle butterfly over the 16 tx lanes (same ty = same warp half) ----
#pragma unroll
    for (int off = 1; off < 16; off <<= 1) {
#pragma unroll
        for (int r = 0; r < 8; r++) {
            float ov = __shfl_xor_sync(0xFFFFFFFFu, bestv[r], off);
            int   oi = __shfl_xor_sync(0xFFFFFFFFu, besti[r], off);
            if (ov < bestv[r] || (ov == bestv[r] && oi < besti[r])) {
                bestv[r] = ov; besti[r] = oi;
            }
        }
    }

    if (tx == 0) {
#pragma unroll
        for (int r = 0; r < 8; r++) {
            int gi = yq * 64 + ql + r;
            int yb = besti[r] >> 6;
            int xb = besti[r] & 63;
            int o0 = (b * 2 + 0) * HW + gi;
            int o1 = (b * 2 + 1) * HW + gi;
            int o2 = NB * 2 * HW + b * HW + gi;
            if (o0 < out_elems) out[o0] = (float)yb;
            if (o1 < out_elems) out[o1] = (float)xb;
            if (o2 < out_elems) out[o2] = bestv[r];
        }
    }
}

extern "C" void kernel_launch(void* const* d_in, const int* in_sizes, int n_in,
                              void* d_out, int out_size) {
    int ia = -1, ib = -1;
    for (int i = 0; i < n_in; i++) {
        if (in_sizes[i] == IMG_ELEMS || in_sizes[i] == IMG_BYTES) {
            if (ia < 0) ia = i;
            else if (ib < 0) ib = i;
        }
    }
    if (ib < 0) {
        ia = -1; ib = -1;
        for (int i = 0; i < n_in; i++) {
            if (ia < 0 || in_sizes[i] > in_sizes[ia]) { ib = ia; ia = i; }
            else if (ib < 0 || in_sizes[i] > in_sizes[ib]) { ib = i; }
        }
        if (ia > ib) { int tmp = ia; ia = ib; ib = tmp; }
    }
    const float* s = (const float*)d_in[ia];
    const float* t = (const float*)d_in[ib];

    float* out = (float*)d_out;
    int out_elems = out_size < OUT_ELEMS_EXPECTED ? out_size : OUT_ELEMS_EXPECTED;

    nn_fused<<<NB * 64, 128>>>(s, t, out, out_elems);
}